// round 14
// baseline (speedup 1.0000x reference)
#include <cuda_runtime.h>
#include <cuda_bf16.h>
#include <math.h>

// ---------------------------------------------------------------------------
// BCEDecorrelatedLoss, 3 kernels, ALL with grid >= 148 blocks (low-grid
// dependent kernels are empirically throttled on this part), no same-address
// atomics, no threadfences:
//   1) pair:     O(N^2) packed-f32x2 pass -> g_p4[js][i] (producer-coalesced)
//   2) reduce:   256 blocks, coalesced gather + 12 fp64 moments -> g_partT
//   3) finalize: 256 blocks (255 exit instantly); block 0 combines + outputs
// ---------------------------------------------------------------------------

#define BLK      128
#define IPT      4            // i's per thread (2 packed f32x2 groups)
#define NPACK    (IPT/2)
#define ITILE    (BLK*IPT)    // 512
#define JCH      256          // j's per pair block
#define MAXN     8192
#define MAXSPLIT (MAXN/JCH)   // 32
#define NRB      256          // reduce blocks (32 rows each)

typedef unsigned long long ull;
#define ABSM 0x7fffffff7fffffffULL

#define ADD2(d, a, b) asm("add.rn.f32x2 %0, %1, %2;" : "=l"(d) : "l"(a), "l"(b))
#define MUL2(d, a, b) asm("mul.rn.f32x2 %0, %1, %2;" : "=l"(d) : "l"(a), "l"(b))
#define FMA2(d, a, b, c) asm("fma.rn.f32x2 %0, %1, %2, %3;" : "=l"(d) : "l"(a), "l"(b), "l"(c))
#define PACK2(d, lo, hi) asm("mov.b64 %0, {%1, %2};" : "=l"(d) : "f"(lo), "f"(hi))

__device__ float4 g_p4[MAXSPLIT][MAXN];   // {A, B, AB, pad}
__device__ double g_partT[12][NRB];       // transposed block partials

__global__ __launch_bounds__(BLK)
void pair_kernel(const float* __restrict__ x, const float* __restrict__ e,
                 const float* __restrict__ w, int n)
{
    // j-tile: {-x,-x,-e,-e} float4 (LDS.128) + {w,w} float2 (LDS.64)
    __shared__ float4 sxe[JCH];
    __shared__ float2 swd[JCH];
    const int js = blockIdx.y;
    const int j0 = js * JCH;
    const int t  = threadIdx.x;

#pragma unroll
    for (int jj = t; jj < JCH; jj += BLK) {
        int j = j0 + jj;
        bool ok = (j < n);
        float xv = ok ? x[j] : 0.0f;
        float ev = ok ? e[j] : 0.0f;
        float wv = ok ? w[j] : 0.0f;
        sxe[jj] = make_float4(-xv, -xv, -ev, -ev);
        swd[jj] = make_float2(wv, wv);
    }
    __syncthreads();

    const int ibase = blockIdx.x * ITILE + t;
    ull xi2[NPACK], ei2[NPACK];
    ull accA[NPACK], accB[NPACK], accAB[NPACK];
#pragma unroll
    for (int g = 0; g < NPACK; g++) {
        int ilo = ibase + (2 * g) * BLK;
        int ihi = ibase + (2 * g + 1) * BLK;
        float xlo = (ilo < n) ? x[ilo] : 0.0f;
        float xhi = (ihi < n) ? x[ihi] : 0.0f;
        float elo = (ilo < n) ? e[ilo] : 0.0f;
        float ehi = (ihi < n) ? e[ihi] : 0.0f;
        PACK2(xi2[g], xlo, xhi);
        PACK2(ei2[g], elo, ehi);
        accA[g] = 0ULL; accB[g] = 0ULL; accAB[g] = 0ULL;
    }

    const ull* pwd = (const ull*)swd;
#pragma unroll 8
    for (int k = 0; k < JCH; k++) {
        const float4 xe = sxe[k];            // LDS.128 broadcast
        const ull nxj = ((const ull*)&xe)[0];
        const ull nej = ((const ull*)&xe)[1];
        const ull wj  = pwd[k];              // LDS.64 broadcast
#pragma unroll
        for (int g = 0; g < NPACK; g++) {
            ull dx, de, awj;
            ADD2(dx, xi2[g], nxj);     // packed fma pipe
            ADD2(de, ei2[g], nej);
            dx &= ABSM;                // LOP3 -> alu pipe
            de &= ABSM;
            MUL2(awj, dx, wj);                  // |dx|*wj
            ADD2(accA[g], accA[g], awj);        // accA += |dx|*wj
            FMA2(accAB[g], awj, de, accAB[g]);  // accAB += |dx|*wj*|de|
            FMA2(accB[g], de, wj, accB[g]);     // accB += |de|*wj
        }
    }

#pragma unroll
    for (int g = 0; g < NPACK; g++) {
        int ilo = ibase + (2 * g) * BLK;
        int ihi = ibase + (2 * g + 1) * BLK;
        float2 a = *(float2*)&accA[g];
        float2 b = *(float2*)&accB[g];
        float2 c = *(float2*)&accAB[g];
        if (ilo < n) g_p4[js][ilo] = make_float4(a.x, b.x, c.x, 0.0f);
        if (ihi < n) g_p4[js][ihi] = make_float4(a.y, b.y, c.y, 0.0f);
    }
}

// 256 blocks; block b owns 32 consecutive rows. Warp w (0..7) owns js-chunk
// [4w, 4w+4): 4 coalesced LDG.128 per lane. smem combine -> warp 0 computes
// the 12 fp64 moments -> g_partT[k][b]. No atomics, no fences, no tail.
__global__ __launch_bounds__(256)
void reduce_kernel(const float* __restrict__ x, const float* __restrict__ y,
                   const float* __restrict__ e, const float* __restrict__ w,
                   int n, int jsplit)
{
    __shared__ float sA[8][32], sB[8][32], sAB[8][32];
    const int tid  = threadIdx.x;
    const int wid  = tid >> 5;
    const int lane = tid & 31;
    const int i    = blockIdx.x * 32 + lane;

    float ra = 0.f, rb = 0.f, rab = 0.f;
    const int jsbase = wid * (MAXSPLIT / 8);   // 4 js per warp
    if (i < n) {
#pragma unroll
        for (int u = 0; u < MAXSPLIT / 8; u++) {
            int js = jsbase + u;
            if (js < jsplit) {
                float4 p = g_p4[js][i];
                ra += p.x; rb += p.y; rab += p.z;
            }
        }
    }
    sA[wid][lane] = ra; sB[wid][lane] = rb; sAB[wid][lane] = rab;
    __syncthreads();

    if (wid == 0) {
        double s[12];
#pragma unroll
        for (int k = 0; k < 12; k++) s[k] = 0.0;
        if (i < n) {
            float fra = 0.f, frb = 0.f, frab = 0.f;
#pragma unroll
            for (int ww = 0; ww < 8; ww++) {
                fra += sA[ww][lane]; frb += sB[ww][lane]; frab += sAB[ww][lane];
            }
            float vi = w[i];
            float xi = x[i];
            float ei = e[i];
            float yi = y[i];
            float sp  = fmaxf(xi, 0.0f) + log1pf(expf(-fabsf(xi)));
            float bce = (sp - xi * yi) * vi;

            s[0]  = (double)vi;
            s[1]  = (double)(vi * fra);
            s[2]  = (double)(vi * frb);
            s[3]  = (double)(vi * frab);
            s[4]  = (double)(vi * fra * frb);
            s[5]  = (double)(vi * fra * fra);
            s[6]  = (double)(vi * frb * frb);
            s[7]  = (double)(vi * xi);
            s[8]  = (double)(vi * xi * xi);
            s[9]  = (double)(vi * ei);
            s[10] = (double)(vi * ei * ei);
            s[11] = (double)bce;
        }
#pragma unroll
        for (int k = 0; k < 12; k++) {
            double v = s[k];
            for (int o = 16; o > 0; o >>= 1)
                v += __shfl_down_sync(0xffffffffu, v, o);
            if (lane == 0) g_partT[k][blockIdx.x] = v;
        }
    }
}

// Launched with 256 blocks to stay above the low-grid throttle; all blocks
// except 0 exit immediately. Block 0: 256 threads, 1 partial column each,
// fully parallel shuffle combine, write the 3 outputs.
__global__ __launch_bounds__(256)
void finalize_kernel(float* __restrict__ out, int n)
{
    if (blockIdx.x != 0) return;

    __shared__ double sm[12][8];
    const int tid  = threadIdx.x;
    const int lane = tid & 31;
    const int wid  = tid >> 5;

    double s[12];
#pragma unroll
    for (int k = 0; k < 12; k++) s[k] = g_partT[k][tid];   // coalesced per k

#pragma unroll
    for (int k = 0; k < 12; k++) {
        double v = s[k];
        for (int o = 16; o > 0; o >>= 1)
            v += __shfl_down_sync(0xffffffffu, v, o);
        if (lane == 0) sm[k][wid] = v;
    }
    __syncthreads();
    if (tid == 0) {
        double tot[12];
#pragma unroll
        for (int k = 0; k < 12; k++) {
            double v = 0.0;
#pragma unroll
            for (int wi = 0; wi < 8; wi++) v += sm[k][wi];
            tot[k] = v;
        }
        double sw  = tot[0];
        double Ra  = tot[1],  Rb  = tot[2],  Rab = tot[3];
        double P   = tot[4],  Qa  = tot[5],  Qb  = tot[6];
        double Vx  = tot[7],  Vx2 = tot[8];
        double Ve  = tot[9],  Ve2 = tot[10];
        double Sbce = tot[11];

        double isw  = 1.0 / sw;
        double isw2 = isw * isw;
        double isw3 = isw2 * isw;
        double isw4 = isw2 * isw2;

        double num  = Rab * isw2 - 2.0 * P * isw3 + Ra * Rb * isw4;
        double dena = 2.0 * Vx2 * isw - 2.0 * Vx * Vx * isw2
                    - 2.0 * Qa * isw3 + Ra * Ra * isw4;
        double denb = 2.0 * Ve2 * isw - 2.0 * Ve * Ve * isw2
                    - 2.0 * Qb * isw3 + Rb * Rb * isw4;

        double disco = num / sqrt(dena * denb);
        double bce   = Sbce / (double)n;

        out[0] = (float)bce;
        out[1] = (float)disco;
        out[2] = (float)(bce + 0.1 * disco);
    }
}

extern "C" void kernel_launch(void* const* d_in, const int* in_sizes, int n_in,
                              void* d_out, int out_size)
{
    const float* x = (const float*)d_in[0];   // outputs (logits)
    const float* y = (const float*)d_in[1];   // labels
    const float* e = (const float*)d_in[2];   // event
    const float* w = (const float*)d_in[3];   // weights
    float* out = (float*)d_out;
    const int n = in_sizes[0];

    int itiles = (n + ITILE - 1) / ITILE;     // 16 for n=8192
    int jsplit = (n + JCH - 1) / JCH;         // 32 for n=8192
    if (jsplit > MAXSPLIT) jsplit = MAXSPLIT;

    dim3 grid(itiles, jsplit);                // 512 blocks
    pair_kernel<<<grid, BLK>>>(x, e, w, n);
    reduce_kernel<<<NRB, 256>>>(x, y, e, w, n, jsplit);
    finalize_kernel<<<NRB, 256>>>(out, n);
}

// round 17
// speedup vs baseline: 1.6435x; 1.6435x over previous
#include <cuda_runtime.h>
#include <cuda_bf16.h>
#include <math.h>

// ---------------------------------------------------------------------------
// BCEDecorrelatedLoss, 3 kernels, all measured-good pieces:
//   1) pair (1024 blocks): O(N^2) packed-f32x2 pass -> g_p4[js][i]
//   2) reduce (256 blocks): coalesced gather + 12 fp64 moments -> g_partT
//      (no fences, no atomics, no tail)
//   3) finalize (256-block launch; block 0 works): combine + outputs
// ---------------------------------------------------------------------------

#define BLK      128
#define IPT      4            // i's per thread (2 packed f32x2 groups)
#define NPACK    (IPT/2)
#define ITILE    (BLK*IPT)    // 512
#define JCH      128          // j's per pair block
#define MAXN     8192
#define MAXSPLIT (MAXN/JCH)   // 64
#define NRB      256          // reduce blocks (32 rows each)

typedef unsigned long long ull;
#define ABSM 0x7fffffff7fffffffULL

#define ADD2(d, a, b) asm("add.rn.f32x2 %0, %1, %2;" : "=l"(d) : "l"(a), "l"(b))
#define MUL2(d, a, b) asm("mul.rn.f32x2 %0, %1, %2;" : "=l"(d) : "l"(a), "l"(b))
#define FMA2(d, a, b, c) asm("fma.rn.f32x2 %0, %1, %2, %3;" : "=l"(d) : "l"(a), "l"(b), "l"(c))
#define PACK2(d, lo, hi) asm("mov.b64 %0, {%1, %2};" : "=l"(d) : "f"(lo), "f"(hi))

__device__ float4 g_p4[MAXSPLIT][MAXN];   // {A, B, AB, pad}, producer-coalesced
__device__ double g_partT[12][NRB];       // transposed block partials

__global__ __launch_bounds__(BLK)
void pair_kernel(const float* __restrict__ x, const float* __restrict__ e,
                 const float* __restrict__ w, int n)
{
    // j-tile: {-x,-x,-e,-e} float4 (LDS.128) + {w,w} float2 (LDS.64)
    __shared__ float4 sxe[JCH];
    __shared__ float2 swd[JCH];
    const int js = blockIdx.y;
    const int j0 = js * JCH;
    const int t  = threadIdx.x;

    {   // BLK == JCH: one j per thread
        int j = j0 + t;
        bool ok = (j < n);
        float xv = ok ? x[j] : 0.0f;
        float ev = ok ? e[j] : 0.0f;
        float wv = ok ? w[j] : 0.0f;
        sxe[t] = make_float4(-xv, -xv, -ev, -ev);
        swd[t] = make_float2(wv, wv);
    }
    __syncthreads();

    const int ibase = blockIdx.x * ITILE + t;
    ull xi2[NPACK], ei2[NPACK];
    ull accA[NPACK], accB[NPACK], accAB[NPACK];
#pragma unroll
    for (int g = 0; g < NPACK; g++) {
        int ilo = ibase + (2 * g) * BLK;
        int ihi = ibase + (2 * g + 1) * BLK;
        float xlo = (ilo < n) ? x[ilo] : 0.0f;
        float xhi = (ihi < n) ? x[ihi] : 0.0f;
        float elo = (ilo < n) ? e[ilo] : 0.0f;
        float ehi = (ihi < n) ? e[ihi] : 0.0f;
        PACK2(xi2[g], xlo, xhi);
        PACK2(ei2[g], elo, ehi);
        accA[g] = 0ULL; accB[g] = 0ULL; accAB[g] = 0ULL;
    }

    const ull* pwd = (const ull*)swd;
#pragma unroll 8
    for (int k = 0; k < JCH; k++) {
        const float4 xe = sxe[k];            // LDS.128 broadcast
        const ull nxj = ((const ull*)&xe)[0];
        const ull nej = ((const ull*)&xe)[1];
        const ull wj  = pwd[k];              // LDS.64 broadcast
#pragma unroll
        for (int g = 0; g < NPACK; g++) {
            ull dx, de, awj;
            ADD2(dx, xi2[g], nxj);     // packed fma pipe
            ADD2(de, ei2[g], nej);
            dx &= ABSM;                // LOP3 -> alu pipe
            de &= ABSM;
            MUL2(awj, dx, wj);                  // |dx|*wj
            ADD2(accA[g], accA[g], awj);        // accA += |dx|*wj
            FMA2(accAB[g], awj, de, accAB[g]);  // accAB += |dx|*wj*|de|
            FMA2(accB[g], de, wj, accB[g]);     // accB += |de|*wj
        }
    }

#pragma unroll
    for (int g = 0; g < NPACK; g++) {
        int ilo = ibase + (2 * g) * BLK;
        int ihi = ibase + (2 * g + 1) * BLK;
        float2 a = *(float2*)&accA[g];
        float2 b = *(float2*)&accB[g];
        float2 c = *(float2*)&accAB[g];
        if (ilo < n) g_p4[js][ilo] = make_float4(a.x, b.x, c.x, 0.0f);
        if (ihi < n) g_p4[js][ihi] = make_float4(a.y, b.y, c.y, 0.0f);
    }
}

// 256 blocks; block b owns 32 consecutive rows. Warp w (0..7) owns js-chunk
// [8w, 8w+8): 8 coalesced LDG.128 per lane (512B/warp each, MLP=8).
// smem combine -> warp 0 computes the 12 fp64 moments -> g_partT[k][b].
__global__ __launch_bounds__(256)
void reduce_kernel(const float* __restrict__ x, const float* __restrict__ y,
                   const float* __restrict__ e, const float* __restrict__ w,
                   int n, int jsplit)
{
    __shared__ float sA[8][32], sB[8][32], sAB[8][32];
    const int tid  = threadIdx.x;
    const int wid  = tid >> 5;
    const int lane = tid & 31;
    const int i    = blockIdx.x * 32 + lane;

    float ra = 0.f, rb = 0.f, rab = 0.f;
    const int jsbase = wid * (MAXSPLIT / 8);   // 8 js per warp
    if (i < n) {
#pragma unroll
        for (int u = 0; u < MAXSPLIT / 8; u++) {
            int js = jsbase + u;
            if (js < jsplit) {
                float4 p = g_p4[js][i];
                ra += p.x; rb += p.y; rab += p.z;
            }
        }
    }
    sA[wid][lane] = ra; sB[wid][lane] = rb; sAB[wid][lane] = rab;
    __syncthreads();

    if (wid == 0) {
        double s[12];
#pragma unroll
        for (int k = 0; k < 12; k++) s[k] = 0.0;
        if (i < n) {
            float fra = 0.f, frb = 0.f, frab = 0.f;
#pragma unroll
            for (int ww = 0; ww < 8; ww++) {
                fra += sA[ww][lane]; frb += sB[ww][lane]; frab += sAB[ww][lane];
            }
            float vi = w[i];
            float xi = x[i];
            float ei = e[i];
            float yi = y[i];
            float sp  = fmaxf(xi, 0.0f) + log1pf(expf(-fabsf(xi)));
            float bce = (sp - xi * yi) * vi;

            s[0]  = (double)vi;
            s[1]  = (double)(vi * fra);
            s[2]  = (double)(vi * frb);
            s[3]  = (double)(vi * frab);
            s[4]  = (double)(vi * fra * frb);
            s[5]  = (double)(vi * fra * fra);
            s[6]  = (double)(vi * frb * frb);
            s[7]  = (double)(vi * xi);
            s[8]  = (double)(vi * xi * xi);
            s[9]  = (double)(vi * ei);
            s[10] = (double)(vi * ei * ei);
            s[11] = (double)bce;
        }
#pragma unroll
        for (int k = 0; k < 12; k++) {
            double v = s[k];
            for (int o = 16; o > 0; o >>= 1)
                v += __shfl_down_sync(0xffffffffu, v, o);
            if (lane == 0) g_partT[k][blockIdx.x] = v;
        }
    }
}

// 256-block launch (above the low-grid throttle); blocks != 0 exit at once.
// Block 0: 256 threads, one partial column each, parallel shuffle combine.
__global__ __launch_bounds__(256)
void finalize_kernel(float* __restrict__ out, int n)
{
    if (blockIdx.x != 0) return;

    __shared__ double sm[12][8];
    const int tid  = threadIdx.x;
    const int lane = tid & 31;
    const int wid  = tid >> 5;

    double s[12];
#pragma unroll
    for (int k = 0; k < 12; k++) s[k] = g_partT[k][tid];   // coalesced per k

#pragma unroll
    for (int k = 0; k < 12; k++) {
        double v = s[k];
        for (int o = 16; o > 0; o >>= 1)
            v += __shfl_down_sync(0xffffffffu, v, o);
        if (lane == 0) sm[k][wid] = v;
    }
    __syncthreads();
    if (tid == 0) {
        double tot[12];
#pragma unroll
        for (int k = 0; k < 12; k++) {
            double v = 0.0;
#pragma unroll
            for (int wi = 0; wi < 8; wi++) v += sm[k][wi];
            tot[k] = v;
        }
        double sw  = tot[0];
        double Ra  = tot[1],  Rb  = tot[2],  Rab = tot[3];
        double P   = tot[4],  Qa  = tot[5],  Qb  = tot[6];
        double Vx  = tot[7],  Vx2 = tot[8];
        double Ve  = tot[9],  Ve2 = tot[10];
        double Sbce = tot[11];

        double isw  = 1.0 / sw;
        double isw2 = isw * isw;
        double isw3 = isw2 * isw;
        double isw4 = isw2 * isw2;

        double num  = Rab * isw2 - 2.0 * P * isw3 + Ra * Rb * isw4;
        double dena = 2.0 * Vx2 * isw - 2.0 * Vx * Vx * isw2
                    - 2.0 * Qa * isw3 + Ra * Ra * isw4;
        double denb = 2.0 * Ve2 * isw - 2.0 * Ve * Ve * isw2
                    - 2.0 * Qb * isw3 + Rb * Rb * isw4;

        double disco = num / sqrt(dena * denb);
        double bce   = Sbce / (double)n;

        out[0] = (float)bce;
        out[1] = (float)disco;
        out[2] = (float)(bce + 0.1 * disco);
    }
}

extern "C" void kernel_launch(void* const* d_in, const int* in_sizes, int n_in,
                              void* d_out, int out_size)
{
    const float* x = (const float*)d_in[0];   // outputs (logits)
    const float* y = (const float*)d_in[1];   // labels
    const float* e = (const float*)d_in[2];   // event
    const float* w = (const float*)d_in[3];   // weights
    float* out = (float*)d_out;
    const int n = in_sizes[0];

    int itiles = (n + ITILE - 1) / ITILE;     // 16 for n=8192
    int jsplit = (n + JCH - 1) / JCH;         // 64 for n=8192
    if (jsplit > MAXSPLIT) jsplit = MAXSPLIT;

    dim3 grid(itiles, jsplit);                // 1024 blocks
    pair_kernel<<<grid, BLK>>>(x, e, w, n);
    reduce_kernel<<<NRB, 256>>>(x, y, e, w, n, jsplit);
    finalize_kernel<<<NRB, 256>>>(out, n);
}